// round 2
// baseline (speedup 1.0000x reference)
#include <cuda_runtime.h>
#include <cuda_bf16.h>

#define NLEVELS 16
#define TSIZE   (1u << 19)
#define HIDDEN  32

// s_l = 16 * 2^(l/3) - 1  (B = exp(ln(512/16)/15) = 2^(1/3)), computed in double, stored f32
__constant__ float c_scales[NLEVELS] = {
    15.0f,
    19.158736798317971f,
    24.398416831491190f,
    31.0f,
    39.317473596635942f,
    49.796833662982379f,
    63.0f,
    79.634947193271885f,
    100.59366732596476f,
    127.0f,
    160.26989438654377f,
    202.18733465192952f,
    255.0f,
    321.53978877308754f,
    405.37466930385904f,
    511.0f
};

__global__ __launch_bounds__(128)
void field_fused_kernel(const float* __restrict__ x,
                        const float* __restrict__ table,
                        const float* __restrict__ W0,
                        const float* __restrict__ b0,
                        const float* __restrict__ W1,
                        const float* __restrict__ b1,
                        const float* __restrict__ Wout,
                        const float* __restrict__ bout,
                        float* __restrict__ out,
                        int n)
{
    // ---- stage all MLP weights in shared memory (broadcast reads later) ----
    __shared__ float sW0[35 * 32];   // (L*F+3, 32) row-major
    __shared__ float sW1[32 * 32];
    __shared__ float sb0[32];
    __shared__ float sb1[32];
    __shared__ float sWout[32];
    __shared__ float sbout;

    const int tid = threadIdx.x;
    for (int i = tid; i < 35 * 32; i += blockDim.x) sW0[i] = W0[i];
    for (int i = tid; i < 32 * 32; i += blockDim.x) sW1[i] = W1[i];
    if (tid < 32) {
        sb0[tid]   = b0[tid];
        sb1[tid]   = b1[tid];
        sWout[tid] = Wout[tid];   // (32,1) -> 32 contiguous floats
    }
    if (tid == 0) sbout = bout[0];
    __syncthreads();

    const int gid = blockIdx.x * blockDim.x + tid;
    if (gid >= n) return;

    // ---- load point, normalize (SCALE = 1) ----
    const float xn0 = (x[3 * gid + 0] + 1.0f) * 0.5f;
    const float xn1 = (x[3 * gid + 1] + 1.0f) * 0.5f;
    const float xn2 = (x[3 * gid + 2] + 1.0f) * 0.5f;

    // ---- layer-0 accumulator: start with bias + xn contribution ----
    float h[HIDDEN];
    #pragma unroll
    for (int j = 0; j < HIDDEN; j++) {
        h[j] = sb0[j] + xn0 * sW0[0 * 32 + j]
                      + xn1 * sW0[1 * 32 + j]
                      + xn2 * sW0[2 * 32 + j];
    }

    // ---- hash-grid encode, folding each level's 2 features into h ----
    #pragma unroll
    for (int l = 0; l < NLEVELS; l++) {
        const float s = c_scales[l];
        const float p0 = xn0 * s, p1 = xn1 * s, p2 = xn2 * s;
        const float f0 = floorf(p0), f1 = floorf(p1), f2 = floorf(p2);
        const float w0 = p0 - f0, w1 = p1 - f1, w2 = p2 - f2;
        const unsigned i0 = (unsigned)f0;
        const unsigned i1 = (unsigned)f1;
        const unsigned i2 = (unsigned)f2;

        // per-axis hashed values for the two corner positions
        const unsigned hx0 = i0;                               // prime 1
        const unsigned hx1 = i0 + 1u;
        const unsigned hy0 = i1 * 2654435761u;
        const unsigned hy1 = (i1 + 1u) * 2654435761u;
        const unsigned hz0 = i2 * 805459861u;
        const unsigned hz1 = (i2 + 1u) * 805459861u;

        const float2* __restrict__ tbl =
            reinterpret_cast<const float2*>(table) + (size_t)l * TSIZE;

        float a0 = 0.0f, a1 = 0.0f;
        #pragma unroll
        for (int c = 0; c < 8; c++) {
            const unsigned hx = (c & 1) ? hx1 : hx0;
            const unsigned hy = (c & 2) ? hy1 : hy0;
            const unsigned hz = (c & 4) ? hz1 : hz0;
            const unsigned idx = (hx ^ hy ^ hz) & (TSIZE - 1u);
            const float wt = ((c & 1) ? w0 : 1.0f - w0)
                           * ((c & 2) ? w1 : 1.0f - w1)
                           * ((c & 4) ? w2 : 1.0f - w2);
            const float2 g = __ldg(tbl + idx);
            a0 += wt * g.x;
            a1 += wt * g.y;
        }

        // fold the two features into layer 0 (rows 3+2l, 4+2l of W0)
        const float* wr0 = &sW0[(3 + 2 * l) * 32];
        const float* wr1 = &sW0[(4 + 2 * l) * 32];
        #pragma unroll
        for (int j = 0; j < HIDDEN; j++) {
            h[j] += a0 * wr0[j] + a1 * wr1[j];
        }
    }

    // ---- ELU ----
    #pragma unroll
    for (int j = 0; j < HIDDEN; j++) {
        h[j] = h[j] > 0.0f ? h[j] : expm1f(h[j]);
    }

    // ---- layer 1 ----
    float h2[HIDDEN];
    #pragma unroll
    for (int j = 0; j < HIDDEN; j++) h2[j] = sb1[j];
    #pragma unroll
    for (int i = 0; i < HIDDEN; i++) {
        const float f = h[i];
        const float* wr = &sW1[i * 32];
        #pragma unroll
        for (int j = 0; j < HIDDEN; j++) h2[j] += f * wr[j];
    }
    #pragma unroll
    for (int j = 0; j < HIDDEN; j++) {
        h2[j] = h2[j] > 0.0f ? h2[j] : expm1f(h2[j]);
    }

    // ---- output layer ----
    float o = sbout;
    #pragma unroll
    for (int j = 0; j < HIDDEN; j++) o += h2[j] * sWout[j];

    out[gid] = o;
}

extern "C" void kernel_launch(void* const* d_in, const int* in_sizes, int n_in,
                              void* d_out, int out_size)
{
    const float* x     = (const float*)d_in[0];
    const float* table = (const float*)d_in[1];
    const float* W0    = (const float*)d_in[2];
    const float* b0    = (const float*)d_in[3];
    const float* W1    = (const float*)d_in[4];
    const float* b1    = (const float*)d_in[5];
    const float* Wout  = (const float*)d_in[6];
    const float* bout  = (const float*)d_in[7];
    float* out = (float*)d_out;

    const int n = in_sizes[0] / 3;   // x is (N,3)
    const int threads = 128;
    const int blocks = (n + threads - 1) / threads;
    field_fused_kernel<<<blocks, threads>>>(x, table, W0, b0, W1, b1,
                                            Wout, bout, out, n);
}

// round 3
// speedup vs baseline: 1.2706x; 1.2706x over previous
#include <cuda_runtime.h>
#include <cuda_bf16.h>

#define NLEVELS 16
#define TSIZE   (1u << 19)
#define HIDDEN  32
#define NPTS_MAX 2000000
#define CELL_BITS 7
#define CELLS_AXIS (1 << CELL_BITS)                 // 128
#define NCELLS (1u << (3 * CELL_BITS))              // 2^21
#define SCAN_BLK 1024
#define NPART (NCELLS / SCAN_BLK)                   // 2048

// ---- static scratch (no allocations allowed) ----
__device__ unsigned g_cell_count[NCELLS];
__device__ unsigned g_cell_start[NCELLS];
__device__ unsigned g_partials[NPART];
__device__ float4   g_pts[NPTS_MAX];

// s_l = 16 * 2^(l/3) - 1
__constant__ float c_scales[NLEVELS] = {
    15.0f, 19.158736798317971f, 24.398416831491190f, 31.0f,
    39.317473596635942f, 49.796833662982379f, 63.0f, 79.634947193271885f,
    100.59366732596476f, 127.0f, 160.26989438654377f, 202.18733465192952f,
    255.0f, 321.53978877308754f, 405.37466930385904f, 511.0f
};

__device__ __forceinline__ unsigned expand3(unsigned v) {
    v &= 0x3FFu;
    v = (v | (v << 16)) & 0x030000FFu;
    v = (v | (v << 8))  & 0x0300F00Fu;
    v = (v | (v << 4))  & 0x030C30C3u;
    v = (v | (v << 2))  & 0x09249249u;
    return v;
}

__device__ __forceinline__ unsigned cell_code(float xn0, float xn1, float xn2) {
    int c0 = min(CELLS_AXIS - 1, max(0, (int)(xn0 * (float)CELLS_AXIS)));
    int c1 = min(CELLS_AXIS - 1, max(0, (int)(xn1 * (float)CELLS_AXIS)));
    int c2 = min(CELLS_AXIS - 1, max(0, (int)(xn2 * (float)CELLS_AXIS)));
    return expand3((unsigned)c0) | (expand3((unsigned)c1) << 1) | (expand3((unsigned)c2) << 2);
}

// ---- sort pipeline ----
__global__ void zero_counts_kernel() {
    unsigned i = blockIdx.x * blockDim.x + threadIdx.x;
    if (i < NCELLS) g_cell_count[i] = 0u;
}

__global__ void hist_kernel(const float* __restrict__ x, int n) {
    int i = blockIdx.x * blockDim.x + threadIdx.x;
    if (i >= n) return;
    const float xn0 = (x[3 * i + 0] + 1.0f) * 0.5f;
    const float xn1 = (x[3 * i + 1] + 1.0f) * 0.5f;
    const float xn2 = (x[3 * i + 2] + 1.0f) * 0.5f;
    atomicAdd(&g_cell_count[cell_code(xn0, xn1, xn2)], 1u);
}

// exclusive scan, stage 1: per-block scan of 1024 counts + block total
__global__ void scan1_kernel() {
    __shared__ unsigned s[SCAN_BLK];
    const unsigned tid = threadIdx.x;
    const unsigned g = blockIdx.x * SCAN_BLK + tid;
    const unsigned v = g_cell_count[g];
    s[tid] = v;
    __syncthreads();
    #pragma unroll
    for (int off = 1; off < SCAN_BLK; off <<= 1) {
        unsigned t = (tid >= (unsigned)off) ? s[tid - off] : 0u;
        __syncthreads();
        s[tid] += t;
        __syncthreads();
    }
    g_cell_start[g] = s[tid] - v;          // exclusive within block
    if (tid == SCAN_BLK - 1) g_partials[blockIdx.x] = s[tid];
}

// stage 2: exclusive scan of the 2048 block totals (single block)
__global__ void scan2_kernel() {
    __shared__ unsigned s[SCAN_BLK];
    const unsigned tid = threadIdx.x;
    const unsigned a = g_partials[2 * tid];
    const unsigned b = g_partials[2 * tid + 1];
    s[tid] = a + b;
    __syncthreads();
    #pragma unroll
    for (int off = 1; off < SCAN_BLK; off <<= 1) {
        unsigned t = (tid >= (unsigned)off) ? s[tid - off] : 0u;
        __syncthreads();
        s[tid] += t;
        __syncthreads();
    }
    const unsigned excl = s[tid] - (a + b);
    g_partials[2 * tid]     = excl;
    g_partials[2 * tid + 1] = excl + a;
}

// stage 3: add block offsets
__global__ void scan3_kernel() {
    const unsigned g = blockIdx.x * SCAN_BLK + threadIdx.x;
    g_cell_start[g] += g_partials[blockIdx.x];
}

// scatter points into spatially-sorted order (consumes g_cell_start as cursors)
__global__ void scatter_kernel(const float* __restrict__ x, int n) {
    int i = blockIdx.x * blockDim.x + threadIdx.x;
    if (i >= n) return;
    const float x0 = x[3 * i + 0];
    const float x1 = x[3 * i + 1];
    const float x2 = x[3 * i + 2];
    const float xn0 = (x0 + 1.0f) * 0.5f;
    const float xn1 = (x1 + 1.0f) * 0.5f;
    const float xn2 = (x2 + 1.0f) * 0.5f;
    const unsigned pos = atomicAdd(&g_cell_start[cell_code(xn0, xn1, xn2)], 1u);
    g_pts[pos] = make_float4(xn0, xn1, xn2, __uint_as_float((unsigned)i));
}

// ---- fused hash-encode + MLP over sorted points ----
__global__ __launch_bounds__(128)
void field_fused_kernel(const float* __restrict__ table,
                        const float* __restrict__ W0,
                        const float* __restrict__ b0,
                        const float* __restrict__ W1,
                        const float* __restrict__ b1,
                        const float* __restrict__ Wout,
                        const float* __restrict__ bout,
                        float* __restrict__ out,
                        int n)
{
    __shared__ float sW0[35 * 32];
    __shared__ float sW1[32 * 32];
    __shared__ float sb0[32];
    __shared__ float sb1[32];
    __shared__ float sWout[32];
    __shared__ float sbout;

    const int tid = threadIdx.x;
    for (int i = tid; i < 35 * 32; i += blockDim.x) sW0[i] = W0[i];
    for (int i = tid; i < 32 * 32; i += blockDim.x) sW1[i] = W1[i];
    if (tid < 32) {
        sb0[tid]   = b0[tid];
        sb1[tid]   = b1[tid];
        sWout[tid] = Wout[tid];
    }
    if (tid == 0) sbout = bout[0];
    __syncthreads();

    const int gid = blockIdx.x * blockDim.x + tid;
    if (gid >= n) return;

    const float4 pt = g_pts[gid];
    const float xn0 = pt.x, xn1 = pt.y, xn2 = pt.z;
    const unsigned oidx = __float_as_uint(pt.w);

    float h[HIDDEN];
    #pragma unroll
    for (int j = 0; j < HIDDEN; j++) {
        h[j] = sb0[j] + xn0 * sW0[0 * 32 + j]
                      + xn1 * sW0[1 * 32 + j]
                      + xn2 * sW0[2 * 32 + j];
    }

    #pragma unroll
    for (int l = 0; l < NLEVELS; l++) {
        const float s = c_scales[l];
        const float p0 = xn0 * s, p1 = xn1 * s, p2 = xn2 * s;
        const float f0 = floorf(p0), f1 = floorf(p1), f2 = floorf(p2);
        const float w0 = p0 - f0, w1 = p1 - f1, w2 = p2 - f2;
        const unsigned i0 = (unsigned)f0;
        const unsigned i1 = (unsigned)f1;
        const unsigned i2 = (unsigned)f2;

        const unsigned hx0 = i0;
        const unsigned hx1 = i0 + 1u;
        const unsigned hy0 = i1 * 2654435761u;
        const unsigned hy1 = (i1 + 1u) * 2654435761u;
        const unsigned hz0 = i2 * 805459861u;
        const unsigned hz1 = (i2 + 1u) * 805459861u;

        const float2* __restrict__ tbl =
            reinterpret_cast<const float2*>(table) + (size_t)l * TSIZE;

        float a0 = 0.0f, a1 = 0.0f;
        #pragma unroll
        for (int c = 0; c < 8; c++) {
            const unsigned hx = (c & 1) ? hx1 : hx0;
            const unsigned hy = (c & 2) ? hy1 : hy0;
            const unsigned hz = (c & 4) ? hz1 : hz0;
            const unsigned idx = (hx ^ hy ^ hz) & (TSIZE - 1u);
            const float wt = ((c & 1) ? w0 : 1.0f - w0)
                           * ((c & 2) ? w1 : 1.0f - w1)
                           * ((c & 4) ? w2 : 1.0f - w2);
            const float2 g = __ldg(tbl + idx);
            a0 += wt * g.x;
            a1 += wt * g.y;
        }

        const float* wr0 = &sW0[(3 + 2 * l) * 32];
        const float* wr1 = &sW0[(4 + 2 * l) * 32];
        #pragma unroll
        for (int j = 0; j < HIDDEN; j++) {
            h[j] += a0 * wr0[j] + a1 * wr1[j];
        }
    }

    #pragma unroll
    for (int j = 0; j < HIDDEN; j++) {
        h[j] = h[j] > 0.0f ? h[j] : expm1f(h[j]);
    }

    float h2[HIDDEN];
    #pragma unroll
    for (int j = 0; j < HIDDEN; j++) h2[j] = sb1[j];
    #pragma unroll
    for (int i = 0; i < HIDDEN; i++) {
        const float f = h[i];
        const float* wr = &sW1[i * 32];
        #pragma unroll
        for (int j = 0; j < HIDDEN; j++) h2[j] += f * wr[j];
    }
    #pragma unroll
    for (int j = 0; j < HIDDEN; j++) {
        h2[j] = h2[j] > 0.0f ? h2[j] : expm1f(h2[j]);
    }

    float o = sbout;
    #pragma unroll
    for (int j = 0; j < HIDDEN; j++) o += h2[j] * sWout[j];

    out[oidx] = o;
}

extern "C" void kernel_launch(void* const* d_in, const int* in_sizes, int n_in,
                              void* d_out, int out_size)
{
    const float* x     = (const float*)d_in[0];
    const float* table = (const float*)d_in[1];
    const float* W0    = (const float*)d_in[2];
    const float* b0    = (const float*)d_in[3];
    const float* W1    = (const float*)d_in[4];
    const float* b1    = (const float*)d_in[5];
    const float* Wout  = (const float*)d_in[6];
    const float* bout  = (const float*)d_in[7];
    float* out = (float*)d_out;

    const int n = in_sizes[0] / 3;

    // 1) spatial counting sort by 128^3 Morton cell
    zero_counts_kernel<<<NCELLS / 1024, 1024>>>();
    hist_kernel<<<(n + 255) / 256, 256>>>(x, n);
    scan1_kernel<<<NPART, SCAN_BLK>>>();
    scan2_kernel<<<1, SCAN_BLK>>>();
    scan3_kernel<<<NPART, SCAN_BLK>>>();
    scatter_kernel<<<(n + 255) / 256, 256>>>(x, n);

    // 2) fused encode + MLP over sorted points
    const int threads = 128;
    field_fused_kernel<<<(n + threads - 1) / threads, threads>>>(
        table, W0, b0, W1, b1, Wout, bout, out, n);
}

// round 4
// speedup vs baseline: 1.3871x; 1.0917x over previous
#include <cuda_runtime.h>
#include <cuda_bf16.h>

typedef unsigned long long u64;

#define NLEVELS 16
#define TSIZE   (1u << 19)
#define HIDDEN  32
#define NPTS_MAX 2000000
#define CELL_BITS 7
#define CELLS_AXIS (1 << CELL_BITS)
#define NCELLS (1u << (3 * CELL_BITS))
#define SCAN_BLK 1024
#define NPART (NCELLS / SCAN_BLK)

// ---- static scratch ----
__device__ unsigned g_cell_count[NCELLS];
__device__ unsigned g_cell_start[NCELLS];
__device__ unsigned g_partials[NPART];
__device__ float4   g_pts[NPTS_MAX];

__constant__ float c_scales[NLEVELS] = {
    15.0f, 19.158736798317971f, 24.398416831491190f, 31.0f,
    39.317473596635942f, 49.796833662982379f, 63.0f, 79.634947193271885f,
    100.59366732596476f, 127.0f, 160.26989438654377f, 202.18733465192952f,
    255.0f, 321.53978877308754f, 405.37466930385904f, 511.0f
};

// ---- packed f32x2 helpers ----
__device__ __forceinline__ u64 pack2(float lo, float hi) {
    u64 r; asm("mov.b64 %0, {%1, %2};" : "=l"(r) : "f"(lo), "f"(hi)); return r;
}
__device__ __forceinline__ void unpack2(u64 v, float& lo, float& hi) {
    asm("mov.b64 {%0, %1}, %2;" : "=f"(lo), "=f"(hi) : "l"(v));
}
__device__ __forceinline__ u64 ffma2(u64 a, u64 b, u64 c) {
    u64 d; asm("fma.rn.f32x2 %0, %1, %2, %3;" : "=l"(d) : "l"(a), "l"(b), "l"(c)); return d;
}

__device__ __forceinline__ unsigned expand3(unsigned v) {
    v &= 0x3FFu;
    v = (v | (v << 16)) & 0x030000FFu;
    v = (v | (v << 8))  & 0x0300F00Fu;
    v = (v | (v << 4))  & 0x030C30C3u;
    v = (v | (v << 2))  & 0x09249249u;
    return v;
}

__device__ __forceinline__ unsigned cell_code(float xn0, float xn1, float xn2) {
    int c0 = min(CELLS_AXIS - 1, max(0, (int)(xn0 * (float)CELLS_AXIS)));
    int c1 = min(CELLS_AXIS - 1, max(0, (int)(xn1 * (float)CELLS_AXIS)));
    int c2 = min(CELLS_AXIS - 1, max(0, (int)(xn2 * (float)CELLS_AXIS)));
    return expand3((unsigned)c0) | (expand3((unsigned)c1) << 1) | (expand3((unsigned)c2) << 2);
}

// ---- sort pipeline ----
__global__ void zero_counts_kernel() {
    unsigned i = blockIdx.x * blockDim.x + threadIdx.x;
    reinterpret_cast<uint4*>(g_cell_count)[i] = make_uint4(0u, 0u, 0u, 0u);
}

__global__ void hist_kernel(const float* __restrict__ x, int n) {
    int i = blockIdx.x * blockDim.x + threadIdx.x;
    if (i >= n) return;
    const float xn0 = (x[3 * i + 0] + 1.0f) * 0.5f;
    const float xn1 = (x[3 * i + 1] + 1.0f) * 0.5f;
    const float xn2 = (x[3 * i + 2] + 1.0f) * 0.5f;
    atomicAdd(&g_cell_count[cell_code(xn0, xn1, xn2)], 1u);
}

// block-wide inclusive scan of v; returns inclusive prefix; total via last thread
__device__ __forceinline__ unsigned block_incl_scan(unsigned v, unsigned tid) {
    __shared__ unsigned warp_sums[32];
    unsigned inc = v;
    #pragma unroll
    for (int off = 1; off < 32; off <<= 1) {
        unsigned t = __shfl_up_sync(~0u, inc, off);
        if ((tid & 31u) >= (unsigned)off) inc += t;
    }
    if ((tid & 31u) == 31u) warp_sums[tid >> 5] = inc;
    __syncthreads();
    if (tid < 32) {
        unsigned s = warp_sums[tid];
        #pragma unroll
        for (int off = 1; off < 32; off <<= 1) {
            unsigned t = __shfl_up_sync(~0u, s, off);
            if (tid >= (unsigned)off) s += t;
        }
        warp_sums[tid] = s;
    }
    __syncthreads();
    unsigned base = (tid >= 32u) ? warp_sums[(tid >> 5) - 1u] : 0u;
    return base + inc;
}

__global__ void scan1_kernel() {
    const unsigned tid = threadIdx.x;
    const unsigned g = blockIdx.x * SCAN_BLK + tid;
    const unsigned v = g_cell_count[g];
    const unsigned inc = block_incl_scan(v, tid);
    g_cell_start[g] = inc - v;
    if (tid == SCAN_BLK - 1) g_partials[blockIdx.x] = inc;
}

__global__ void scan2_kernel() {
    const unsigned tid = threadIdx.x;
    const unsigned a = g_partials[2 * tid];
    const unsigned b = g_partials[2 * tid + 1];
    const unsigned s = a + b;
    const unsigned inc = block_incl_scan(s, tid);
    const unsigned excl = inc - s;
    g_partials[2 * tid]     = excl;
    g_partials[2 * tid + 1] = excl + a;
}

__global__ void scan3_kernel() {
    const unsigned g = blockIdx.x * SCAN_BLK + threadIdx.x;
    g_cell_start[g] += g_partials[blockIdx.x];
}

__global__ void scatter_kernel(const float* __restrict__ x, int n) {
    int i = blockIdx.x * blockDim.x + threadIdx.x;
    if (i >= n) return;
    const float xn0 = (x[3 * i + 0] + 1.0f) * 0.5f;
    const float xn1 = (x[3 * i + 1] + 1.0f) * 0.5f;
    const float xn2 = (x[3 * i + 2] + 1.0f) * 0.5f;
    const unsigned pos = atomicAdd(&g_cell_start[cell_code(xn0, xn1, xn2)], 1u);
    g_pts[pos] = make_float4(xn0, xn1, xn2, __uint_as_float((unsigned)i));
}

// ---- fused hash-encode + MLP, 2 points per thread, packed f32x2 math ----
__global__ __launch_bounds__(128)
void field_fused_kernel(const float* __restrict__ table,
                        const float* __restrict__ W0,
                        const float* __restrict__ b0,
                        const float* __restrict__ W1,
                        const float* __restrict__ b1,
                        const float* __restrict__ Wout,
                        const float* __restrict__ bout,
                        float* __restrict__ out,
                        int n)
{
    // weights duplicated into 64-bit (w,w) pairs for direct packed operands
    __shared__ u64 sW0[35 * 32];
    __shared__ u64 sW1[32 * 32];
    __shared__ u64 sb0[32];
    __shared__ u64 sb1[32];
    __shared__ u64 sWout[32];
    __shared__ float sbout;

    const int tid = threadIdx.x;
    for (int i = tid; i < 35 * 32; i += blockDim.x) { float w = W0[i]; sW0[i] = pack2(w, w); }
    for (int i = tid; i < 32 * 32; i += blockDim.x) { float w = W1[i]; sW1[i] = pack2(w, w); }
    if (tid < 32) {
        float v0 = b0[tid];   sb0[tid]   = pack2(v0, v0);
        float v1 = b1[tid];   sb1[tid]   = pack2(v1, v1);
        float vo = Wout[tid]; sWout[tid] = pack2(vo, vo);
    }
    if (tid == 0) sbout = bout[0];
    __syncthreads();

    const int gid = blockIdx.x * blockDim.x + tid;
    const int iA = 2 * gid;
    if (iA >= n) return;
    const int iB = (iA + 1 < n) ? iA + 1 : iA;

    const float4 ptA = g_pts[iA];
    const float4 ptB = g_pts[iB];
    const unsigned oiA = __float_as_uint(ptA.w);
    const unsigned oiB = __float_as_uint(ptB.w);

    const u64 xp0 = pack2(ptA.x, ptB.x);
    const u64 xp1 = pack2(ptA.y, ptB.y);
    const u64 xp2 = pack2(ptA.z, ptB.z);

    // ---- layer-0 accumulator (packed): bias + coords ----
    u64 h[HIDDEN];
    #pragma unroll
    for (int j = 0; j < HIDDEN; j++) {
        h[j] = ffma2(xp0, sW0[0 * 32 + j],
               ffma2(xp1, sW0[1 * 32 + j],
               ffma2(xp2, sW0[2 * 32 + j], sb0[j])));
    }

    // ---- hash-grid levels, folded into h ----
    #pragma unroll 4
    for (int l = 0; l < NLEVELS; l++) {
        const float s = c_scales[l];
        const float2* __restrict__ tbl =
            reinterpret_cast<const float2*>(table) + (size_t)l * TSIZE;

        // point A
        const float pA0 = ptA.x * s, pA1 = ptA.y * s, pA2 = ptA.z * s;
        const float fA0 = floorf(pA0), fA1 = floorf(pA1), fA2 = floorf(pA2);
        const float wA0 = pA0 - fA0, wA1 = pA1 - fA1, wA2 = pA2 - fA2;
        const unsigned iA0 = (unsigned)fA0, iA1 = (unsigned)fA1, iA2 = (unsigned)fA2;
        const unsigned hxA0 = iA0,            hxA1 = iA0 + 1u;
        const unsigned hyA0 = iA1 * 2654435761u, hyA1 = (iA1 + 1u) * 2654435761u;
        const unsigned hzA0 = iA2 * 805459861u,  hzA1 = (iA2 + 1u) * 805459861u;

        // point B
        const float pB0 = ptB.x * s, pB1 = ptB.y * s, pB2 = ptB.z * s;
        const float fB0 = floorf(pB0), fB1 = floorf(pB1), fB2 = floorf(pB2);
        const float wB0 = pB0 - fB0, wB1 = pB1 - fB1, wB2 = pB2 - fB2;
        const unsigned iB0 = (unsigned)fB0, iB1 = (unsigned)fB1, iB2 = (unsigned)fB2;
        const unsigned hxB0 = iB0,            hxB1 = iB0 + 1u;
        const unsigned hyB0 = iB1 * 2654435761u, hyB1 = (iB1 + 1u) * 2654435761u;
        const unsigned hzB0 = iB2 * 805459861u,  hzB1 = (iB2 + 1u) * 805459861u;

        u64 a0 = 0ull, a1 = 0ull;
        #pragma unroll
        for (int c = 0; c < 8; c++) {
            const unsigned idxA = (((c & 1) ? hxA1 : hxA0) ^ ((c & 2) ? hyA1 : hyA0)
                                 ^ ((c & 4) ? hzA1 : hzA0)) & (TSIZE - 1u);
            const unsigned idxB = (((c & 1) ? hxB1 : hxB0) ^ ((c & 2) ? hyB1 : hyB0)
                                 ^ ((c & 4) ? hzB1 : hzB0)) & (TSIZE - 1u);
            const float wtA = ((c & 1) ? wA0 : 1.0f - wA0)
                            * ((c & 2) ? wA1 : 1.0f - wA1)
                            * ((c & 4) ? wA2 : 1.0f - wA2);
            const float wtB = ((c & 1) ? wB0 : 1.0f - wB0)
                            * ((c & 2) ? wB1 : 1.0f - wB1)
                            * ((c & 4) ? wB2 : 1.0f - wB2);
            const float2 gA = __ldg(tbl + idxA);
            const float2 gB = __ldg(tbl + idxB);
            const u64 wtp = pack2(wtA, wtB);
            a0 = ffma2(wtp, pack2(gA.x, gB.x), a0);
            a1 = ffma2(wtp, pack2(gA.y, gB.y), a1);
        }

        const u64* wr0 = &sW0[(3 + 2 * l) * 32];
        const u64* wr1 = &sW0[(4 + 2 * l) * 32];
        #pragma unroll
        for (int j = 0; j < HIDDEN; j++) {
            h[j] = ffma2(a0, wr0[j], ffma2(a1, wr1[j], h[j]));
        }
    }

    // ---- ELU on h (componentwise) ----
    #pragma unroll
    for (int j = 0; j < HIDDEN; j++) {
        float a, b;
        unpack2(h[j], a, b);
        a = a > 0.0f ? a : expm1f(a);
        b = b > 0.0f ? b : expm1f(b);
        h[j] = pack2(a, b);
    }

    // ---- layer 1 + output, no h2 array: o += elu(dot)*Wout[j] ----
    u64 o = pack2(sbout, sbout);
    #pragma unroll 4
    for (int j = 0; j < HIDDEN; j++) {
        u64 t = sb1[j];
        #pragma unroll
        for (int i = 0; i < HIDDEN; i++) {
            t = ffma2(h[i], sW1[i * 32 + j], t);
        }
        float a, b;
        unpack2(t, a, b);
        a = a > 0.0f ? a : expm1f(a);
        b = b > 0.0f ? b : expm1f(b);
        o = ffma2(pack2(a, b), sWout[j], o);
    }

    float oA, oB;
    unpack2(o, oA, oB);
    out[oiA] = oA;
    if (iA + 1 < n) out[oiB] = oB;
}

extern "C" void kernel_launch(void* const* d_in, const int* in_sizes, int n_in,
                              void* d_out, int out_size)
{
    const float* x     = (const float*)d_in[0];
    const float* table = (const float*)d_in[1];
    const float* W0    = (const float*)d_in[2];
    const float* b0    = (const float*)d_in[3];
    const float* W1    = (const float*)d_in[4];
    const float* b1    = (const float*)d_in[5];
    const float* Wout  = (const float*)d_in[6];
    const float* bout  = (const float*)d_in[7];
    float* out = (float*)d_out;

    const int n = in_sizes[0] / 3;

    zero_counts_kernel<<<NCELLS / 4 / 1024, 1024>>>();
    hist_kernel<<<(n + 255) / 256, 256>>>(x, n);
    scan1_kernel<<<NPART, SCAN_BLK>>>();
    scan2_kernel<<<1, SCAN_BLK>>>();
    scan3_kernel<<<NPART, SCAN_BLK>>>();
    scatter_kernel<<<(n + 255) / 256, 256>>>(x, n);

    const int npair = (n + 1) / 2;
    const int threads = 128;
    field_fused_kernel<<<(npair + threads - 1) / threads, threads>>>(
        table, W0, b0, W1, b1, Wout, bout, out, n);
}